// round 1
// baseline (speedup 1.0000x reference)
#include <cuda_runtime.h>

#define Bn 4
#define Tn 2048
#define Cn 1024
#define HDn 64
#define NROWS (Bn*Tn)   // 8192

// Scratch (allowed: __device__ globals, allocated at module load)
__device__ float g_q[NROWS*HDn];
__device__ float g_k[NROWS*HDn];
__device__ float g_v[NROWS*HDn];
__device__ float g_s[NROWS*Tn];       // 8192*2048 = 16.7M floats = 64MB (fits L2)
__device__ float g_m[NROWS];
__device__ float g_iz[NROWS];

// ---------------------------------------------------------------------------
// Kernel A: fused QKV projection.  [8192,1024] @ [1024, 64]x3
// 128 CTAs x 256 threads; CTA tile 64 rows x 192 cols; thread tile 4x12.
// ---------------------------------------------------------------------------
__global__ __launch_bounds__(256) void qkv_kernel(
    const float* __restrict__ x,
    const float* __restrict__ Wq,
    const float* __restrict__ Wk,
    const float* __restrict__ Wv)
{
    __shared__ float xs[32][68];    // x tile transposed [k][row]
    __shared__ float ws[32][196];   // W tile [k][Q|K|V cols]

    const int row0 = blockIdx.x * 64;
    const int tid  = threadIdx.x;
    const int tx   = tid & 15;      // col group
    const int ty   = tid >> 4;      // row group

    float acc[4][12];
    #pragma unroll
    for (int i = 0; i < 4; i++)
        #pragma unroll
        for (int j = 0; j < 12; j++) acc[i][j] = 0.f;

    for (int k0 = 0; k0 < Cn; k0 += 32) {
        __syncthreads();
        // load x tile 64 rows x 32 k, transposed into smem
        for (int i = tid; i < 64*8; i += 256) {
            int r = i >> 3, c4 = i & 7;
            float4 v = *(const float4*)&x[(size_t)(row0 + r)*Cn + k0 + c4*4];
            xs[c4*4+0][r] = v.x; xs[c4*4+1][r] = v.y;
            xs[c4*4+2][r] = v.z; xs[c4*4+3][r] = v.w;
        }
        // load W tile: ws[kk][0:64)=Wq, [64:128)=Wk, [128:192)=Wv
        for (int i = tid; i < 32*48; i += 256) {
            int kk = i / 48, j = i - kk*48;
            int which = j >> 4, c4 = j & 15;
            const float* W = (which == 0) ? Wq : ((which == 1) ? Wk : Wv);
            float4 v = *(const float4*)&W[(size_t)(k0+kk)*HDn + c4*4];
            *(float4*)&ws[kk][which*64 + c4*4] = v;
        }
        __syncthreads();
        #pragma unroll
        for (int kk = 0; kk < 32; kk++) {
            float a[4], bb[12];
            *(float4*)&a[0]  = *(const float4*)&xs[kk][ty*4];
            *(float4*)&bb[0] = *(const float4*)&ws[kk][tx*4];
            *(float4*)&bb[4] = *(const float4*)&ws[kk][64 + tx*4];
            *(float4*)&bb[8] = *(const float4*)&ws[kk][128 + tx*4];
            #pragma unroll
            for (int i = 0; i < 4; i++)
                #pragma unroll
                for (int j = 0; j < 12; j++)
                    acc[i][j] = fmaf(a[i], bb[j], acc[i][j]);
        }
    }
    #pragma unroll
    for (int i = 0; i < 4; i++) {
        size_t row = (size_t)(row0 + ty*4 + i);
        *(float4*)&g_q[row*HDn + tx*4] = *(float4*)&acc[i][0];
        *(float4*)&g_k[row*HDn + tx*4] = *(float4*)&acc[i][4];
        *(float4*)&g_v[row*HDn + tx*4] = *(float4*)&acc[i][8];
    }
}

// ---------------------------------------------------------------------------
// Kernel B1: scores z = 8 * Q K^T, full (unmasked) TxT per batch.
// grid (s_blocks=16, row_blocks=64); CTA tile 128x128; thread tile 8x8.
// ---------------------------------------------------------------------------
__global__ __launch_bounds__(256) void scores_kernel()
{
    __shared__ float qT[32][132];   // [k][row]
    __shared__ float kT[32][132];   // [k][key]

    const int s0    = blockIdx.x * 128;
    const int row0  = blockIdx.y * 128;
    const int b     = row0 / Tn;              // 128 | 2048 -> single batch per CTA
    const int krow0 = b * Tn + s0;
    const int tid   = threadIdx.x;
    const int tx    = tid & 15;
    const int ty    = tid >> 4;

    float acc[8][8];
    #pragma unroll
    for (int i = 0; i < 8; i++)
        #pragma unroll
        for (int j = 0; j < 8; j++) acc[i][j] = 0.f;

    for (int k0 = 0; k0 < HDn; k0 += 32) {
        __syncthreads();
        for (int i = tid; i < 128*8; i += 256) {
            int r = i >> 3, c4 = i & 7;
            float4 v = *(const float4*)&g_q[(size_t)(row0 + r)*HDn + k0 + c4*4];
            qT[c4*4+0][r] = v.x; qT[c4*4+1][r] = v.y;
            qT[c4*4+2][r] = v.z; qT[c4*4+3][r] = v.w;
            float4 w = *(const float4*)&g_k[(size_t)(krow0 + r)*HDn + k0 + c4*4];
            kT[c4*4+0][r] = w.x; kT[c4*4+1][r] = w.y;
            kT[c4*4+2][r] = w.z; kT[c4*4+3][r] = w.w;
        }
        __syncthreads();
        #pragma unroll
        for (int kk = 0; kk < 32; kk++) {
            float a[8], bb[8];
            *(float4*)&a[0]  = *(const float4*)&qT[kk][ty*4];
            *(float4*)&a[4]  = *(const float4*)&qT[kk][64 + ty*4];
            *(float4*)&bb[0] = *(const float4*)&kT[kk][tx*4];
            *(float4*)&bb[4] = *(const float4*)&kT[kk][64 + tx*4];
            #pragma unroll
            for (int i = 0; i < 8; i++)
                #pragma unroll
                for (int j = 0; j < 8; j++)
                    acc[i][j] = fmaf(a[i], bb[j], acc[i][j]);
        }
    }
    #pragma unroll
    for (int i = 0; i < 8; i++) {
        int row = row0 + ((i >> 2) ? 64 : 0) + ty*4 + (i & 3);
        float* dst = &g_s[(size_t)row*Tn + s0];
        float4 o0 = make_float4(acc[i][0]*8.f, acc[i][1]*8.f, acc[i][2]*8.f, acc[i][3]*8.f);
        float4 o1 = make_float4(acc[i][4]*8.f, acc[i][5]*8.f, acc[i][6]*8.f, acc[i][7]*8.f);
        *(float4*)&dst[tx*4]      = o0;
        *(float4*)&dst[64 + tx*4] = o1;
    }
}

// ---------------------------------------------------------------------------
// Kernel B2: per-row full-row softmax stats (m, 1/Z). One warp per row.
// ---------------------------------------------------------------------------
__global__ __launch_bounds__(256) void stats_kernel()
{
    const int row  = blockIdx.x * 8 + (threadIdx.x >> 5);
    const int lane = threadIdx.x & 31;
    const float* zr = &g_s[(size_t)row * Tn];

    float4 v[16];
    #pragma unroll
    for (int w = 0; w < 16; w++)
        v[w] = *(const float4*)&zr[w*128 + lane*4];

    float m = -1e30f;
    #pragma unroll
    for (int w = 0; w < 16; w++)
        m = fmaxf(m, fmaxf(fmaxf(v[w].x, v[w].y), fmaxf(v[w].z, v[w].w)));
    #pragma unroll
    for (int off = 16; off > 0; off >>= 1)
        m = fmaxf(m, __shfl_xor_sync(0xffffffffu, m, off));

    float Z = 0.f;
    #pragma unroll
    for (int w = 0; w < 16; w++)
        Z += __expf(v[w].x - m) + __expf(v[w].y - m)
           + __expf(v[w].z - m) + __expf(v[w].w - m);
    #pragma unroll
    for (int off = 16; off > 0; off >>= 1)
        Z += __shfl_xor_sync(0xffffffffu, Z, off);

    if (lane == 0) { g_m[row] = m; g_iz[row] = 1.f / Z; }
}

// ---------------------------------------------------------------------------
// Kernel B3: out[t] = sum_{s<=t} exp(w1) v[s] / sum_{s<=t} exp(w1),
//            w1 = exp(z - m)/Z.  CTA = 64 rows; loop causal s-tiles of 32.
// Reverse CTA order so heaviest (largest t) blocks launch first.
// ---------------------------------------------------------------------------
__global__ __launch_bounds__(128) void out_kernel(float* __restrict__ out)
{
    __shared__ float eT[32][68];     // [s][row]
    __shared__ float vs[32][68];     // [s][d]
    __shared__ float msh[64], ish[64], dsh[64];

    const int rb   = (int)gridDim.x - 1 - (int)blockIdx.x;
    const int row0 = rb * 64;                // global row
    const int b    = row0 / Tn;
    const int t0   = row0 - b * Tn;
    const int tid  = threadIdx.x;
    const int tx   = tid & 7;                // d group (8 cols each)
    const int ty   = tid >> 3;               // row group (4 rows each)

    if (tid < 64) { msh[tid] = g_m[row0 + tid]; ish[tid] = g_iz[row0 + tid]; }

    float acc[4][8];
    #pragma unroll
    for (int i = 0; i < 4; i++)
        #pragma unroll
        for (int j = 0; j < 8; j++) acc[i][j] = 0.f;

    float den = 0.f;                          // even threads own row tid/2
    const int myrow = tid >> 1;
    const int t_my  = t0 + myrow;
    const int ntiles = t0/32 + 2;             // covers s <= t0+63

    for (int tile = 0; tile < ntiles; tile++) {
        const int s0 = tile * 32;
        __syncthreads();
        // V tile [32 s][64 d]
        for (int i = tid; i < 512; i += 128) {
            int s = i >> 4, d4 = i & 15;
            *(float4*)&vs[s][d4*4] =
                *(const float4*)&g_v[(size_t)(b*Tn + s0 + s)*HDn + d4*4];
        }
        // e = exp(w1) tile, transposed; fused causal mask + den partial
        {
            const float m  = msh[myrow];
            const float iz = ish[myrow];
            const int sb = (tid & 1) * 16;
            const float* zp = &g_s[(size_t)(row0 + myrow)*Tn + s0 + sb];
            float esum = 0.f;
            #pragma unroll
            for (int j = 0; j < 4; j++) {
                float4 z = *(const float4*)&zp[j*4];
                float zz[4] = {z.x, z.y, z.z, z.w};
                #pragma unroll
                for (int c = 0; c < 4; c++) {
                    int s = s0 + sb + j*4 + c;
                    float e = 0.f;
                    if (s <= t_my) {
                        float w1 = __expf(zz[c] - m) * iz;   // in [0,1]
                        e = __expf(w1);
                    }
                    eT[sb + j*4 + c][myrow] = e;
                    esum += e;
                }
            }
            float o = __shfl_down_sync(0xffffffffu, esum, 1);
            if (!(tid & 1)) den += esum + o;
        }
        __syncthreads();
        // GEMM: acc += e^T(row, s) * V(s, d)
        #pragma unroll
        for (int s = 0; s < 32; s++) {
            float a[4], bb[8];
            *(float4*)&a[0]  = *(const float4*)&eT[s][ty*4];
            *(float4*)&bb[0] = *(const float4*)&vs[s][tx*8];
            *(float4*)&bb[4] = *(const float4*)&vs[s][tx*8 + 4];
            #pragma unroll
            for (int i = 0; i < 4; i++)
                #pragma unroll
                for (int j = 0; j < 8; j++)
                    acc[i][j] = fmaf(a[i], bb[j], acc[i][j]);
        }
    }

    if (!(tid & 1)) dsh[myrow] = den;
    __syncthreads();

    #pragma unroll
    for (int i = 0; i < 4; i++) {
        int row = ty*4 + i;
        float inv = 1.f / dsh[row];
        float4 o0 = make_float4(acc[i][0]*inv, acc[i][1]*inv, acc[i][2]*inv, acc[i][3]*inv);
        float4 o1 = make_float4(acc[i][4]*inv, acc[i][5]*inv, acc[i][6]*inv, acc[i][7]*inv);
        size_t o = (size_t)(row0 + row)*HDn + tx*8;
        *(float4*)&out[o]     = o0;
        *(float4*)&out[o + 4] = o1;
    }
}

// ---------------------------------------------------------------------------
extern "C" void kernel_launch(void* const* d_in, const int* in_sizes, int n_in,
                              void* d_out, int out_size)
{
    const float* x  = (const float*)d_in[0];
    const float* Wq = (const float*)d_in[1];
    const float* Wk = (const float*)d_in[2];
    const float* Wv = (const float*)d_in[3];
    float* out = (float*)d_out;

    qkv_kernel<<<NROWS/64, 256>>>(x, Wq, Wk, Wv);
    scores_kernel<<<dim3(Tn/128, NROWS/128), 256>>>();
    stats_kernel<<<NROWS/8, 256>>>();
    out_kernel<<<NROWS/64, 128>>>(out);
}